// round 14
// baseline (speedup 1.0000x reference)
#include <cuda_runtime.h>
#include <cuda_bf16.h>
#include <math.h>
#include <stdint.h>

#define N 8192
#define D 512
#define KSEL 16
#define CCAP 64            // candidate capacity per row
#define FLOORC 64          // histogram floor code (sim >= 32.0)

// ---------------- static device scratch (no runtime allocation) -----------
__device__ __align__(16) __nv_bfloat16 g_xb[(size_t)N * D];        // 8 MB
__device__ __align__(16) uint8_t g_code[(size_t)N * N];            // 64 MB

// ======================= helpers ==========================================
__device__ __forceinline__ uint32_t smem_u32(const void* p) {
    uint32_t a;
    asm("{ .reg .u64 t; cvta.to.shared.u64 t, %1; cvt.u32.u64 %0, t; }"
        : "=r"(a) : "l"(p));
    return a;
}
#define CP_ASYNC16(dst, src) \
    asm volatile("cp.async.cg.shared.global [%0], [%1], 16;" :: "r"(dst), "l"(src))
#define CP_ASYNC_COMMIT() asm volatile("cp.async.commit_group;" ::: "memory")
#define CP_ASYNC_WAIT1()  asm volatile("cp.async.wait_group 1;" ::: "memory")
#define CP_ASYNC_WAIT0()  asm volatile("cp.async.wait_group 0;" ::: "memory")

#define LDSM_X4(r0, r1, r2, r3, addr)                                        \
    asm volatile("ldmatrix.sync.aligned.m8n8.x4.shared.b16 {%0,%1,%2,%3}, [%4];" \
                 : "=r"(r0), "=r"(r1), "=r"(r2), "=r"(r3) : "r"(addr))
#define LDSM_X2(r0, r1, addr)                                                \
    asm volatile("ldmatrix.sync.aligned.m8n8.x2.shared.b16 {%0,%1}, [%2];"   \
                 : "=r"(r0), "=r"(r1) : "r"(addr))

__device__ __forceinline__ void mma_bf16(float* c, const unsigned* a, const unsigned* b)
{
    asm volatile(
        "mma.sync.aligned.m16n8k16.row.col.f32.bf16.bf16.f32 "
        "{%0,%1,%2,%3}, {%4,%5,%6,%7}, {%8,%9}, {%0,%1,%2,%3};\n"
        : "+f"(c[0]), "+f"(c[1]), "+f"(c[2]), "+f"(c[3])
        : "r"(a[0]), "r"(a[1]), "r"(a[2]), "r"(a[3]), "r"(b[0]), "r"(b[1]));
}
__device__ __forceinline__ void stcs4(uint4* p, uint4 v) {
    asm volatile("st.global.cs.v4.u32 [%0], {%1,%2,%3,%4};"
                 :: "l"(p), "r"(v.x), "r"(v.y), "r"(v.z), "r"(v.w) : "memory");
}
__device__ __forceinline__ void stcs4f(float4* p, float4 v) {
    asm volatile("st.global.cs.v4.f32 [%0], {%1,%2,%3,%4};"
                 :: "l"(p), "f"(v.x), "f"(v.y), "f"(v.z), "f"(v.w) : "memory");
}
// monotone fp32 -> uint8 code (0.5 resolution over [0, 127.5])
__device__ __forceinline__ uint32_t code_u8(float a) {
    int v = __float2int_rn(a * 2.0f);
    v = v < 0 ? 0 : (v > 255 ? 255 : v);
    return (uint32_t)v;
}

// ---------------------------------------------------------------------------
// Kernel 0: fused pass-through copy + fp32 -> bf16 convert (one read of x)
// ---------------------------------------------------------------------------
__global__ __launch_bounds__(256) void convert_copy_kernel(const float* __restrict__ x,
                                                           float* __restrict__ out_x)
{
    int i4 = blockIdx.x * 256 + threadIdx.x;
    float4 v = ((const float4*)x)[i4];
    ((float4*)out_x)[i4] = v;
    __nv_bfloat162 lo = __floats2bfloat162_rn(v.x, v.y);
    __nv_bfloat162 hi = __floats2bfloat162_rn(v.z, v.w);
    uint2 packed;
    packed.x = *(unsigned*)&lo;
    packed.y = *(unsigned*)&hi;
    ((uint2*)g_xb)[i4] = packed;
}

// ---------------------------------------------------------------------------
// Kernel 1: codes = quantize(Xb * Xb^T), upper triangle, 1D grid of exactly
// 2080 CTAs (no dead CTAs). Each CTA also zeroes a slab of the adjacency,
// interleaved into the k-loop.
// ---------------------------------------------------------------------------
#define BMg 128
#define BNg 128
#define BKg 64
#define BKP 72                          // 144 B rows: conflict-free LDSM
#define STAGES 3
#define A_UNITS (BMg * BKP)
#define B_UNITS (BNg * BKP)
#define STAGE_UNITS (A_UNITS + B_UNITS)
#define PIPE_BYTES (STAGES * STAGE_UNITS * 2)   // 110592
#define TLD 144                         // code-tile row stride
#define SMEM_GEMM PIPE_BYTES
#define MT 64                           // tile grid dimension
#define NUPPER 2080                     // MT*(MT+1)/2
#define ZCH4 8067                       // float4 per CTA (covers 16M float4)
#define ZPI  1009                       // float4 per CTA per k-iteration

__device__ __forceinline__ void issue_stage(uint32_t sA, uint32_t sB,
                                            int mbase, int nbase, int k0, int tid)
{
#pragma unroll
    for (int i = 0; i < 4; i++) {
        int id  = tid + i * 256;
        int row = id >> 3;
        int c   = id & 7;
        CP_ASYNC16(sA + row * 144 + c * 16,
                   g_xb + (size_t)(mbase + row) * D + k0 + c * 8);
        CP_ASYNC16(sB + row * 144 + c * 16,
                   g_xb + (size_t)(nbase + row) * D + k0 + c * 8);
    }
    CP_ASYNC_COMMIT();
}

__global__ __launch_bounds__(256, 2) void gemm_sym_kernel(float* __restrict__ adj)
{
    // ---- decode linear tile id -> (by, bx), by <= bx ----
    const int lt = blockIdx.x;                 // 0 .. NUPPER-1
    int by;
    {
        const float ff = 2.0f * MT + 1.0f;
        by = (int)floorf((ff - sqrtf(ff * ff - 8.0f * (float)lt)) * 0.5f);
        // fixup against float error; S(b) = b*MT - b*(b-1)/2
        while ((by + 1) * MT - ((by + 1) * by) / 2 <= lt) by++;
        while (by * MT - (by * (by - 1)) / 2 > lt) by--;
    }
    const int bx = by + (lt - (by * MT - (by * (by - 1)) / 2));

    extern __shared__ __align__(16) char smem_raw[];
    __nv_bfloat16* smem = (__nv_bfloat16*)smem_raw;
    const uint32_t sb = smem_u32(smem);

    const int tid  = threadIdx.x;
    const int lane = tid & 31;
    const int wid  = tid >> 5;
    const int wm   = wid >> 2;
    const int wn   = wid & 3;
    const int g    = lane >> 2;
    const int t    = lane & 3;

    const int mbase = by * BMg;
    const int nbase = bx * BNg;

    // zero-fill slab for this CTA
    const size_t zstart = (size_t)lt * ZCH4;
    const size_t ztotal = (size_t)N * N / 4;
    float4* zbase = (float4*)adj + zstart;
    const float4 zv = make_float4(0.f, 0.f, 0.f, 0.f);

    const uint32_t aLaneOff = ((lane & 15) * BKP + (lane >> 4) * 8) * 2 +
                              (wm * 64) * BKP * 2;
    const uint32_t bLaneOff = ((lane & 7) * BKP + ((lane >> 3) & 1) * 8) * 2 +
                              (wn * 32) * BKP * 2;

    float acc[4][4][4];
#pragma unroll
    for (int i = 0; i < 4; i++)
#pragma unroll
        for (int j = 0; j < 4; j++)
#pragma unroll
            for (int q = 0; q < 4; q++) acc[i][j][q] = 0.0f;

#pragma unroll
    for (int s = 0; s < STAGES - 1; s++) {
        uint32_t base = sb + s * STAGE_UNITS * 2;
        issue_stage(base, base + A_UNITS * 2, mbase, nbase, s * BKg, tid);
    }

    const int NT = D / BKg;   // 8
    for (int kt = 0; kt < NT; kt++) {
        CP_ASYNC_WAIT1();
        __syncthreads();

        const int nk = kt + STAGES - 1;
        if (nk < NT) {
            uint32_t base = sb + (nk % STAGES) * STAGE_UNITS * 2;
            issue_stage(base, base + A_UNITS * 2, mbase, nbase, nk * BKg, tid);
        } else {
            CP_ASYNC_COMMIT();   // tail-safe wait_group semantics
        }

        // interleaved adjacency zero-fill (~4 streaming stores / thread)
#pragma unroll
        for (int i = 0; i < 4; i++) {
            int u = kt * ZPI + i * 256 + tid;
            if (u < ZCH4 && zstart + u < ztotal) stcs4f(&zbase[u], zv);
        }

        const uint32_t sA = sb + (kt % STAGES) * STAGE_UNITS * 2;
        const uint32_t sB = sA + A_UNITS * 2;
        const uint32_t aBase = sA + aLaneOff;
        const uint32_t bBase = sB + bLaneOff;

#pragma unroll
        for (int s = 0; s < 4; s++) {
            const uint32_t kOff = s * 32;
            unsigned af[4][4], bfr[4][2];
#pragma unroll
            for (int i = 0; i < 4; i++)
                LDSM_X4(af[i][0], af[i][1], af[i][2], af[i][3],
                        aBase + i * (16 * BKP * 2) + kOff);
#pragma unroll
            for (int j = 0; j < 4; j++)
                LDSM_X2(bfr[j][0], bfr[j][1],
                        bBase + j * (8 * BKP * 2) + kOff);
#pragma unroll
            for (int i = 0; i < 4; i++)
#pragma unroll
                for (int j = 0; j < 4; j++)
                    mma_bf16(acc[i][j], af[i], bfr[j]);
        }
    }
    CP_ASYNC_WAIT0();
    __syncthreads();

    // ---- stage uint8 code tile in smem (reuse pipeline smem) ----
    uint8_t* tile = (uint8_t*)smem;
#pragma unroll
    for (int i = 0; i < 4; i++) {
#pragma unroll
        for (int j = 0; j < 4; j++) {
            const int r0 = wm * 64 + i * 16 + g;
            const int c  = wn * 32 + j * 8 + t * 2;
            uint32_t p01 = code_u8(acc[i][j][0]) | (code_u8(acc[i][j][1]) << 8);
            uint32_t p23 = code_u8(acc[i][j][2]) | (code_u8(acc[i][j][3]) << 8);
            *(uint16_t*)&tile[r0 * TLD + c]       = (uint16_t)p01;
            *(uint16_t*)&tile[(r0 + 8) * TLD + c] = (uint16_t)p23;
        }
    }
    __syncthreads();

    // ---- direct write: 128 rows x 128 bytes (streaming) ----
#pragma unroll
    for (int kk = 0; kk < 4; kk++) {
        int u   = tid + kk * 256;
        int row = u >> 3;
        int seg = u & 7;
        stcs4((uint4*)(g_code + (size_t)(mbase + row) * N + nbase + seg * 16),
              *(const uint4*)&tile[row * TLD + seg * 16]);
    }

    // ---- mirror write: transpose bytes ----
    if (bx != by) {
        const int c = tid & 127;
        const int h = tid >> 7;
        uint8_t* dst = g_code + (size_t)(nbase + c) * N + mbase + h * 64;
#pragma unroll
        for (int q = 0; q < 4; q++) {
            uint32_t w[4];
#pragma unroll
            for (int p = 0; p < 4; p++) {
                int rb = h * 64 + q * 16 + p * 4;
                uint32_t b0 = tile[(rb + 0) * TLD + c];
                uint32_t b1 = tile[(rb + 1) * TLD + c];
                uint32_t b2 = tile[(rb + 2) * TLD + c];
                uint32_t b3 = tile[(rb + 3) * TLD + c];
                w[p] = b0 | (b1 << 8) | (b2 << 16) | (b3 << 24);
            }
            stcs4((uint4*)(dst + q * 16), make_uint4(w[0], w[1], w[2], w[3]));
        }
    }
}

// ---------------------------------------------------------------------------
// Kernel 2: fused select (256-bin floored histogram) + exact fp32 rescore
// (dual-candidate streams per warp) + top-16 scatter.
// ---------------------------------------------------------------------------
__global__ __launch_bounds__(256) void select_rescore_kernel(
    const float* __restrict__ x, float* __restrict__ adj)
{
    __shared__ uint32_t rowbuf[2048];       // 8 KB codes
    __shared__ int hist[256];
    __shared__ __align__(16) float xr[D];   // 2 KB
    __shared__ int   scand[CCAP];
    __shared__ float cv[CCAP];
    __shared__ int   sci[CCAP];
    __shared__ int totalHi, sB, sCnt, sIdx;

    const int row  = blockIdx.x;
    const int tid  = threadIdx.x;
    const int lane = tid & 31;
    const int wid  = tid >> 5;

    hist[tid] = 0;
    if (tid < CCAP) { cv[tid] = -INFINITY; sci[tid] = -1; }
    if (tid == 0) { sIdx = 0; totalHi = 0; }

    const uint4* src = (const uint4*)(g_code + (size_t)row * N);
    ((uint4*)rowbuf)[tid]       = __ldcs(&src[tid]);
    ((uint4*)rowbuf)[tid + 256] = __ldcs(&src[tid + 256]);
    if (tid < D / 4)
        ((float4*)xr)[tid] = ((const float4*)(x + (size_t)row * D))[tid];
    __syncthreads();

    // pass 1: floored histogram
    int myc = 0;
#pragma unroll
    for (int i = 0; i < 8; i++) {
        uint32_t w = rowbuf[tid + i * 256];
#pragma unroll
        for (int b = 0; b < 4; b++) {
            uint32_t v = (w >> (8 * b)) & 255u;
            if (v >= FLOORC) { atomicAdd(&hist[v], 1); myc++; }
        }
    }
#pragma unroll
    for (int off = 16; off > 0; off >>= 1)
        myc += __shfl_down_sync(0xffffffff, myc, off);
    if (lane == 0) atomicAdd(&totalHi, myc);
    __syncthreads();

    // fallback: full histogram (correctness guard; not taken for this data)
    if (totalHi < 32) {
        hist[tid] = 0;
        __syncthreads();
#pragma unroll
        for (int i = 0; i < 8; i++) {
            uint32_t w = rowbuf[tid + i * 256];
#pragma unroll
            for (int b = 0; b < 4; b++)
                atomicAdd(&hist[(w >> (8 * b)) & 255u], 1);
        }
        __syncthreads();
    }

    // boundary scan in warp 0
    if (wid == 0) {
        const int b0 = lane * 8;
        int csum = 0;
#pragma unroll
        for (int k = 0; k < 8; k++) csum += hist[b0 + k];
        int v = csum;
#pragma unroll
        for (int off = 1; off < 32; off <<= 1) {
            int n = __shfl_down_sync(0xffffffff, v, off);
            if (lane + off < 32) v += n;
        }
        int Snext = v - csum;
        if (v >= 32 && Snext < 32) {
            int cum = Snext;
            int b = b0 + 7;
            for (; b >= b0; b--) {
                cum += hist[b];
                if (cum >= 32) break;
            }
            sB = b;
            sCnt = cum;
        }
    }
    __syncthreads();
    const uint32_t B = (uint32_t)sB;

    // pass 2: collect candidate columns into smem
#pragma unroll
    for (int i = 0; i < 8; i++) {
        const int u = tid + i * 256;
        uint32_t w = rowbuf[u];
#pragma unroll
        for (int b = 0; b < 4; b++) {
            uint32_t v = (w >> (8 * b)) & 255u;
            if (v >= B) {
                int slot = atomicAdd(&sIdx, 1);
                if (slot < CCAP) scand[slot] = 4 * u + b;
            }
        }
    }
    __syncthreads();
    const int cnt = (sCnt < CCAP) ? sCnt : CCAP;

    // exact fp32 rescore: each warp walks candidate PAIRS (c, c+8) with two
    // interleaved accumulators to double gather MLP.
    const float4* xr4 = (const float4*)xr;
#pragma unroll
    for (int j = 0; j < CCAP / 16; j++) {
        const int c1 = wid + j * 16;
        const int c2 = wid + 8 + j * 16;
        const bool a1 = (c1 < cnt), a2 = (c2 < cnt);
        const int col1 = a1 ? scand[c1] : 0;
        const int col2 = a2 ? scand[c2] : 0;
        const float4* xc1 = (const float4*)(x + (size_t)col1 * D);
        const float4* xc2 = (const float4*)(x + (size_t)col2 * D);
        float s1 = 0.0f, s2 = 0.0f;
        if (a1 && a2) {
#pragma unroll
            for (int k = 0; k < D / 128; k++) {
                float4 a = xr4[lane + k * 32];
                float4 b1 = xc1[lane + k * 32];
                float4 b2 = xc2[lane + k * 32];
                s1 = fmaf(a.x, b1.x, s1); s2 = fmaf(a.x, b2.x, s2);
                s1 = fmaf(a.y, b1.y, s1); s2 = fmaf(a.y, b2.y, s2);
                s1 = fmaf(a.z, b1.z, s1); s2 = fmaf(a.z, b2.z, s2);
                s1 = fmaf(a.w, b1.w, s1); s2 = fmaf(a.w, b2.w, s2);
            }
        } else if (a1) {
#pragma unroll
            for (int k = 0; k < D / 128; k++) {
                float4 a = xr4[lane + k * 32];
                float4 b1 = xc1[lane + k * 32];
                s1 = fmaf(a.x, b1.x, s1);
                s1 = fmaf(a.y, b1.y, s1);
                s1 = fmaf(a.z, b1.z, s1);
                s1 = fmaf(a.w, b1.w, s1);
            }
        }
#pragma unroll
        for (int off = 16; off > 0; off >>= 1) {
            s1 += __shfl_down_sync(0xffffffff, s1, off);
            s2 += __shfl_down_sync(0xffffffff, s2, off);
        }
        if (lane == 0) {
            if (a1) { cv[c1] = s1; sci[c1] = col1; }
            if (a2) { cv[c2] = s2; sci[c2] = col2; }
        }
    }
    __syncthreads();

    // rank (value desc, col asc on tie) and scatter top-16
    if (tid < cnt) {
        const float v   = cv[tid];
        const int   col = sci[tid];
        int rank = 0;
#pragma unroll
        for (int j2 = 0; j2 < CCAP; j2++) {
            float vj = cv[j2];
            int   cj = sci[j2];
            rank += (vj > v) || (vj == v && cj < col);
        }
        if (rank < KSEL) adj[(size_t)row * N + col] = v;
    }
}

// ---------------------------------------------------------------------------
// Launch
// ---------------------------------------------------------------------------
extern "C" void kernel_launch(void* const* d_in, const int* in_sizes, int n_in,
                              void* d_out, int out_size)
{
    const float* x = (const float*)d_in[0];
    float* out = (float*)d_out;

    float* out_x   = out;
    float* out_adj = out + (size_t)N * D;

    convert_copy_kernel<<<(N * D) / 1024, 256>>>(x, out_x);

    cudaFuncSetAttribute(gemm_sym_kernel,
                         cudaFuncAttributeMaxDynamicSharedMemorySize, SMEM_GEMM);
    gemm_sym_kernel<<<NUPPER, 256, SMEM_GEMM>>>(out_adj);

    select_rescore_kernel<<<N, 256>>>(x, out_adj);
}

// round 15
// speedup vs baseline: 1.0479x; 1.0479x over previous
#include <cuda_runtime.h>
#include <cuda_bf16.h>
#include <math.h>
#include <stdint.h>

#define N 8192
#define D 512
#define KSEL 16
#define CCAP 64            // candidate capacity per row
#define FLOORC 64          // histogram floor code (sim >= 32.0)

// ---------------- static device scratch (no runtime allocation) -----------
__device__ __align__(16) __nv_bfloat16 g_xb[(size_t)N * D];        // 8 MB
__device__ __align__(16) uint8_t g_code[(size_t)N * N];            // 64 MB

// ======================= helpers ==========================================
__device__ __forceinline__ uint32_t smem_u32(const void* p) {
    uint32_t a;
    asm("{ .reg .u64 t; cvta.to.shared.u64 t, %1; cvt.u32.u64 %0, t; }"
        : "=r"(a) : "l"(p));
    return a;
}
#define CP_ASYNC16(dst, src) \
    asm volatile("cp.async.cg.shared.global [%0], [%1], 16;" :: "r"(dst), "l"(src))
#define CP_ASYNC_COMMIT() asm volatile("cp.async.commit_group;" ::: "memory")
#define CP_ASYNC_WAIT1()  asm volatile("cp.async.wait_group 1;" ::: "memory")
#define CP_ASYNC_WAIT0()  asm volatile("cp.async.wait_group 0;" ::: "memory")

#define LDSM_X4(r0, r1, r2, r3, addr)                                        \
    asm volatile("ldmatrix.sync.aligned.m8n8.x4.shared.b16 {%0,%1,%2,%3}, [%4];" \
                 : "=r"(r0), "=r"(r1), "=r"(r2), "=r"(r3) : "r"(addr))
#define LDSM_X2(r0, r1, addr)                                                \
    asm volatile("ldmatrix.sync.aligned.m8n8.x2.shared.b16 {%0,%1}, [%2];"   \
                 : "=r"(r0), "=r"(r1) : "r"(addr))

__device__ __forceinline__ void mma_bf16(float* c, const unsigned* a, const unsigned* b)
{
    asm volatile(
        "mma.sync.aligned.m16n8k16.row.col.f32.bf16.bf16.f32 "
        "{%0,%1,%2,%3}, {%4,%5,%6,%7}, {%8,%9}, {%0,%1,%2,%3};\n"
        : "+f"(c[0]), "+f"(c[1]), "+f"(c[2]), "+f"(c[3])
        : "r"(a[0]), "r"(a[1]), "r"(a[2]), "r"(a[3]), "r"(b[0]), "r"(b[1]));
}
__device__ __forceinline__ void stcs4(uint4* p, uint4 v) {
    asm volatile("st.global.cs.v4.u32 [%0], {%1,%2,%3,%4};"
                 :: "l"(p), "r"(v.x), "r"(v.y), "r"(v.z), "r"(v.w) : "memory");
}
__device__ __forceinline__ void stcs4f(float4* p, float4 v) {
    asm volatile("st.global.cs.v4.f32 [%0], {%1,%2,%3,%4};"
                 :: "l"(p), "f"(v.x), "f"(v.y), "f"(v.z), "f"(v.w) : "memory");
}
// monotone fp32 -> uint8 code (0.5 resolution over [0, 127.5])
__device__ __forceinline__ uint32_t code_u8(float a) {
    int v = __float2int_rn(a * 2.0f);
    v = v < 0 ? 0 : (v > 255 ? 255 : v);
    return (uint32_t)v;
}

// ---------------------------------------------------------------------------
// Kernel 0: fp32 -> bf16 convert only (4 float4/thread for MLP).
// The out_x pass-through copy lives in select_rescore (off the critical path).
// ---------------------------------------------------------------------------
__global__ __launch_bounds__(256) void convert_bf16_kernel(const float* __restrict__ x)
{
#pragma unroll
    for (int i = 0; i < 4; i++) {
        int i4 = blockIdx.x * 1024 + i * 256 + threadIdx.x;
        float4 v = ((const float4*)x)[i4];
        __nv_bfloat162 lo = __floats2bfloat162_rn(v.x, v.y);
        __nv_bfloat162 hi = __floats2bfloat162_rn(v.z, v.w);
        uint2 packed;
        packed.x = *(unsigned*)&lo;
        packed.y = *(unsigned*)&hi;
        ((uint2*)g_xb)[i4] = packed;
    }
}

// ---------------------------------------------------------------------------
// Kernel 1: codes = quantize(Xb * Xb^T), symmetric (bx >= by), 2D grid
// (R13-proven). Upper-triangle CTAs also zero an adjacency slab,
// interleaved into the k-loop.
// ---------------------------------------------------------------------------
#define BMg 128
#define BNg 128
#define BKg 64
#define BKP 72                          // 144 B rows: conflict-free LDSM
#define STAGES 3
#define A_UNITS (BMg * BKP)
#define B_UNITS (BNg * BKP)
#define STAGE_UNITS (A_UNITS + B_UNITS)
#define PIPE_BYTES (STAGES * STAGE_UNITS * 2)   // 110592
#define TLD 144                         // code-tile row stride
#define SMEM_GEMM PIPE_BYTES
#define ZCH4 8067                       // float4 per MMA CTA (covers 16M float4)
#define ZPI  1009                       // float4 per CTA per k-iteration

__device__ __forceinline__ void issue_stage(uint32_t sA, uint32_t sB,
                                            int mbase, int nbase, int k0, int tid)
{
#pragma unroll
    for (int i = 0; i < 4; i++) {
        int id  = tid + i * 256;
        int row = id >> 3;
        int c   = id & 7;
        CP_ASYNC16(sA + row * 144 + c * 16,
                   g_xb + (size_t)(mbase + row) * D + k0 + c * 8);
        CP_ASYNC16(sB + row * 144 + c * 16,
                   g_xb + (size_t)(nbase + row) * D + k0 + c * 8);
    }
    CP_ASYNC_COMMIT();
}

__global__ __launch_bounds__(256, 2) void gemm_sym_kernel(float* __restrict__ adj)
{
    const int bx = blockIdx.x;
    const int by = blockIdx.y;
    if (by > bx) return;

    extern __shared__ __align__(16) char smem_raw[];
    __nv_bfloat16* smem = (__nv_bfloat16*)smem_raw;
    const uint32_t sb = smem_u32(smem);

    const int tid  = threadIdx.x;
    const int lane = tid & 31;
    const int wid  = tid >> 5;
    const int wm   = wid >> 2;
    const int wn   = wid & 3;
    const int g    = lane >> 2;
    const int t    = lane & 3;

    const int mbase = by * BMg;
    const int nbase = bx * BNg;

    // zero-fill slab for this upper-triangle CTA
    const int ztile = by * 64 - (by * (by - 1)) / 2 + (bx - by);  // 0..2079
    const size_t zstart = (size_t)ztile * ZCH4;
    const size_t ztotal = (size_t)N * N / 4;
    float4* zbase = (float4*)adj + zstart;
    const float4 zv = make_float4(0.f, 0.f, 0.f, 0.f);

    const uint32_t aLaneOff = ((lane & 15) * BKP + (lane >> 4) * 8) * 2 +
                              (wm * 64) * BKP * 2;
    const uint32_t bLaneOff = ((lane & 7) * BKP + ((lane >> 3) & 1) * 8) * 2 +
                              (wn * 32) * BKP * 2;

    float acc[4][4][4];
#pragma unroll
    for (int i = 0; i < 4; i++)
#pragma unroll
        for (int j = 0; j < 4; j++)
#pragma unroll
            for (int q = 0; q < 4; q++) acc[i][j][q] = 0.0f;

#pragma unroll
    for (int s = 0; s < STAGES - 1; s++) {
        uint32_t base = sb + s * STAGE_UNITS * 2;
        issue_stage(base, base + A_UNITS * 2, mbase, nbase, s * BKg, tid);
    }

    const int NT = D / BKg;   // 8
    for (int kt = 0; kt < NT; kt++) {
        CP_ASYNC_WAIT1();
        __syncthreads();

        const int nk = kt + STAGES - 1;
        if (nk < NT) {
            uint32_t base = sb + (nk % STAGES) * STAGE_UNITS * 2;
            issue_stage(base, base + A_UNITS * 2, mbase, nbase, nk * BKg, tid);
        } else {
            CP_ASYNC_COMMIT();   // tail-safe wait_group semantics
        }

        // interleaved adjacency zero-fill (~4 streaming stores / thread)
#pragma unroll
        for (int i = 0; i < 4; i++) {
            int u = kt * ZPI + i * 256 + tid;
            if (u < ZCH4 && zstart + u < ztotal) stcs4f(&zbase[u], zv);
        }

        const uint32_t sA = sb + (kt % STAGES) * STAGE_UNITS * 2;
        const uint32_t sB = sA + A_UNITS * 2;
        const uint32_t aBase = sA + aLaneOff;
        const uint32_t bBase = sB + bLaneOff;

#pragma unroll
        for (int s = 0; s < 4; s++) {
            const uint32_t kOff = s * 32;
            unsigned af[4][4], bfr[4][2];
#pragma unroll
            for (int i = 0; i < 4; i++)
                LDSM_X4(af[i][0], af[i][1], af[i][2], af[i][3],
                        aBase + i * (16 * BKP * 2) + kOff);
#pragma unroll
            for (int j = 0; j < 4; j++)
                LDSM_X2(bfr[j][0], bfr[j][1],
                        bBase + j * (8 * BKP * 2) + kOff);
#pragma unroll
            for (int i = 0; i < 4; i++)
#pragma unroll
                for (int j = 0; j < 4; j++)
                    mma_bf16(acc[i][j], af[i], bfr[j]);
        }
    }
    CP_ASYNC_WAIT0();
    __syncthreads();

    // ---- stage uint8 code tile in smem (reuse pipeline smem) ----
    uint8_t* tile = (uint8_t*)smem;
#pragma unroll
    for (int i = 0; i < 4; i++) {
#pragma unroll
        for (int j = 0; j < 4; j++) {
            const int r0 = wm * 64 + i * 16 + g;
            const int c  = wn * 32 + j * 8 + t * 2;
            uint32_t p01 = code_u8(acc[i][j][0]) | (code_u8(acc[i][j][1]) << 8);
            uint32_t p23 = code_u8(acc[i][j][2]) | (code_u8(acc[i][j][3]) << 8);
            *(uint16_t*)&tile[r0 * TLD + c]       = (uint16_t)p01;
            *(uint16_t*)&tile[(r0 + 8) * TLD + c] = (uint16_t)p23;
        }
    }
    __syncthreads();

    // ---- direct write: 128 rows x 128 bytes (streaming) ----
#pragma unroll
    for (int kk = 0; kk < 4; kk++) {
        int u   = tid + kk * 256;
        int row = u >> 3;
        int seg = u & 7;
        stcs4((uint4*)(g_code + (size_t)(mbase + row) * N + nbase + seg * 16),
              *(const uint4*)&tile[row * TLD + seg * 16]);
    }

    // ---- mirror write: transpose bytes ----
    if (bx != by) {
        const int c = tid & 127;
        const int h = tid >> 7;
        uint8_t* dst = g_code + (size_t)(nbase + c) * N + mbase + h * 64;
#pragma unroll
        for (int q = 0; q < 4; q++) {
            uint32_t w[4];
#pragma unroll
            for (int p = 0; p < 4; p++) {
                int rb = h * 64 + q * 16 + p * 4;
                uint32_t b0 = tile[(rb + 0) * TLD + c];
                uint32_t b1 = tile[(rb + 1) * TLD + c];
                uint32_t b2 = tile[(rb + 2) * TLD + c];
                uint32_t b3 = tile[(rb + 3) * TLD + c];
                w[p] = b0 | (b1 << 8) | (b2 << 16) | (b3 << 24);
            }
            stcs4((uint4*)(dst + q * 16), make_uint4(w[0], w[1], w[2], w[3]));
        }
    }
}

// ---------------------------------------------------------------------------
// Kernel 2: fused select (256-bin floored histogram) + exact fp32 rescore +
// top-16 scatter + out_x pass-through copy (R13-proven single-stream rescore).
// ---------------------------------------------------------------------------
__global__ __launch_bounds__(256) void select_rescore_kernel(
    const float* __restrict__ x, float* __restrict__ out_x,
    float* __restrict__ adj)
{
    __shared__ uint32_t rowbuf[2048];       // 8 KB codes
    __shared__ int hist[256];
    __shared__ __align__(16) float xr[D];   // 2 KB
    __shared__ int   scand[CCAP];
    __shared__ float cv[CCAP];
    __shared__ int   sci[CCAP];
    __shared__ int totalHi, sB, sCnt, sIdx;

    const int row  = blockIdx.x;
    const int tid  = threadIdx.x;
    const int lane = tid & 31;
    const int wid  = tid >> 5;

    hist[tid] = 0;
    if (tid < CCAP) { cv[tid] = -INFINITY; sci[tid] = -1; }
    if (tid == 0) { sIdx = 0; totalHi = 0; }

    const uint4* src = (const uint4*)(g_code + (size_t)row * N);
    ((uint4*)rowbuf)[tid]       = __ldcs(&src[tid]);
    ((uint4*)rowbuf)[tid + 256] = __ldcs(&src[tid + 256]);
    if (tid < D / 4) {
        float4 v = ((const float4*)(x + (size_t)row * D))[tid];
        ((float4*)xr)[tid] = v;
        // pass-through copy of x (moved off the pre-GEMM critical path)
        ((float4*)(out_x + (size_t)row * D))[tid] = v;
    }
    __syncthreads();

    // pass 1: floored histogram
    int myc = 0;
#pragma unroll
    for (int i = 0; i < 8; i++) {
        uint32_t w = rowbuf[tid + i * 256];
#pragma unroll
        for (int b = 0; b < 4; b++) {
            uint32_t v = (w >> (8 * b)) & 255u;
            if (v >= FLOORC) { atomicAdd(&hist[v], 1); myc++; }
        }
    }
#pragma unroll
    for (int off = 16; off > 0; off >>= 1)
        myc += __shfl_down_sync(0xffffffff, myc, off);
    if (lane == 0) atomicAdd(&totalHi, myc);
    __syncthreads();

    // fallback: full histogram (correctness guard; not taken for this data)
    if (totalHi < 32) {
        hist[tid] = 0;
        __syncthreads();
#pragma unroll
        for (int i = 0; i < 8; i++) {
            uint32_t w = rowbuf[tid + i * 256];
#pragma unroll
            for (int b = 0; b < 4; b++)
                atomicAdd(&hist[(w >> (8 * b)) & 255u], 1);
        }
        __syncthreads();
    }

    // boundary scan in warp 0
    if (wid == 0) {
        const int b0 = lane * 8;
        int csum = 0;
#pragma unroll
        for (int k = 0; k < 8; k++) csum += hist[b0 + k];
        int v = csum;
#pragma unroll
        for (int off = 1; off < 32; off <<= 1) {
            int n = __shfl_down_sync(0xffffffff, v, off);
            if (lane + off < 32) v += n;
        }
        int Snext = v - csum;
        if (v >= 32 && Snext < 32) {
            int cum = Snext;
            int b = b0 + 7;
            for (; b >= b0; b--) {
                cum += hist[b];
                if (cum >= 32) break;
            }
            sB = b;
            sCnt = cum;
        }
    }
    __syncthreads();
    const uint32_t B = (uint32_t)sB;

    // pass 2: collect candidate columns into smem
#pragma unroll
    for (int i = 0; i < 8; i++) {
        const int u = tid + i * 256;
        uint32_t w = rowbuf[u];
#pragma unroll
        for (int b = 0; b < 4; b++) {
            uint32_t v = (w >> (8 * b)) & 255u;
            if (v >= B) {
                int slot = atomicAdd(&sIdx, 1);
                if (slot < CCAP) scand[slot] = 4 * u + b;
            }
        }
    }
    __syncthreads();
    const int cnt = (sCnt < CCAP) ? sCnt : CCAP;

    // exact fp32 rescore of candidates (float4 gathers from L2-resident x)
    const float4* xr4 = (const float4*)xr;
#pragma unroll
    for (int j = 0; j < CCAP / 8; j++) {
        const int c = wid + j * 8;
        if (c < cnt) {
            const int col = scand[c];
            const float4* xc = (const float4*)(x + (size_t)col * D);
            float sum = 0.0f;
#pragma unroll
            for (int k = 0; k < D / 128; k++) {
                float4 a = xr4[lane + k * 32];
                float4 b = xc[lane + k * 32];
                sum = fmaf(a.x, b.x, sum);
                sum = fmaf(a.y, b.y, sum);
                sum = fmaf(a.z, b.z, sum);
                sum = fmaf(a.w, b.w, sum);
            }
#pragma unroll
            for (int off = 16; off > 0; off >>= 1)
                sum += __shfl_down_sync(0xffffffff, sum, off);
            if (lane == 0) { cv[c] = sum; sci[c] = col; }
        }
    }
    __syncthreads();

    // rank (value desc, col asc on tie) and scatter top-16
    if (tid < cnt) {
        const float v   = cv[tid];
        const int   col = sci[tid];
        int rank = 0;
#pragma unroll
        for (int j2 = 0; j2 < CCAP; j2++) {
            float vj = cv[j2];
            int   cj = sci[j2];
            rank += (vj > v) || (vj == v && cj < col);
        }
        if (rank < KSEL) adj[(size_t)row * N + col] = v;
    }
}

// ---------------------------------------------------------------------------
// Launch
// ---------------------------------------------------------------------------
extern "C" void kernel_launch(void* const* d_in, const int* in_sizes, int n_in,
                              void* d_out, int out_size)
{
    const float* x = (const float*)d_in[0];
    float* out = (float*)d_out;

    float* out_x   = out;
    float* out_adj = out + (size_t)N * D;

    convert_bf16_kernel<<<(N * D) / 4096, 256>>>(x);

    cudaFuncSetAttribute(gemm_sym_kernel,
                         cudaFuncAttributeMaxDynamicSharedMemorySize, SMEM_GEMM);
    dim3 grid(N / BNg, N / BMg);
    gemm_sym_kernel<<<grid, 256, SMEM_GEMM>>>(out_adj);

    select_rescore_kernel<<<N, 256>>>(x, out_x, out_adj);
}